// round 4
// baseline (speedup 1.0000x reference)
#include <cuda_runtime.h>
#include <cuda_bf16.h>
#include <cstdint>

#define H        4096
#define NSTEPS   100
#define IN_DIM   512
#define OUT_DIM  64
#define ND       10          // delay ring slots
#define NB       144         // persistent blocks (<= 148 SMs -> co-resident)
#define TPB      512
#define NGRP     18          // NB*TPB / H
#define NSEG     8           // H / TPB  (phase-A blocks / spike-list segments)
#define DECAY_F  0.9512294245007141f

// ---------------- static device state (no runtime allocation) ----------------
__device__ float         g_Fp[NGRP][ND][H];       // per-group partial future currents (2.95 MB)
__device__ float         g_IIN[NSTEPS * H];       // precomputed input currents (1.6 MB)
__device__ unsigned char g_DPK[(size_t)H * H];    // packed delays, 1..9 (16 MB)
__device__ int           g_spk[H];                // segmented compacted spike list
__device__ int           g_cnt[NSEG];             // per-segment spike counts
__device__ float         g_vsum[H];               // membrane trace sums
__device__ unsigned      g_barA = 0u;             // grid barrier arrive counter
__device__ unsigned      g_barG = 0u;             // grid barrier generation

// ---------------- manual grid barrier (sense via generation counter) ---------
__device__ __forceinline__ void grid_sync() {
    __threadfence();          // publish this thread's global stores
    __syncthreads();
    if (threadIdx.x == 0) {
        unsigned gen = *((volatile unsigned*)&g_barG);  // stable: barrier can't release before we arrive
        unsigned a = atomicAdd(&g_barA, 1u);
        if (a == NB - 1u) {
            g_barA = 0u;
            __threadfence();
            atomicAdd(&g_barG, 1u);                      // release
        } else {
            while (*((volatile unsigned*)&g_barG) == gen) { }
        }
        __threadfence();
    }
    __syncthreads();
}

// ---------------- pre-pass 1: pack int32 delays -> uint8 ---------------------
__global__ void __launch_bounds__(256) pack_kernel(const int* __restrict__ delays) {
    int idx = blockIdx.x * 256 + threadIdx.x;        // over H*H/4 = 4,194,304
    int4 d = ((const int4*)delays)[idx];
    uchar4 p;
    p.x = (unsigned char)d.x; p.y = (unsigned char)d.y;
    p.z = (unsigned char)d.z; p.w = (unsigned char)d.w;
    ((uchar4*)g_DPK)[idx] = p;
}

// ---------------- pre-pass 2: input currents IIN = X @ Win -------------------
#define TCH 10
__global__ void __launch_bounds__(256) iin_kernel(const float* __restrict__ x,
                                                  const float* __restrict__ win) {
    __shared__ float xs[TCH][IN_DIM];
    int j  = blockIdx.x * 256 + threadIdx.x;          // column 0..4095 (grid.x = 16)
    int t0 = blockIdx.y * TCH;                        // step chunk   (grid.y = 10)
    for (int idx = threadIdx.x; idx < TCH * IN_DIM; idx += 256)
        xs[idx >> 9][idx & 511] = x[(t0 + (idx >> 9)) * IN_DIM + (idx & 511)];
    __syncthreads();
    float acc[TCH];
#pragma unroll
    for (int tt = 0; tt < TCH; tt++) acc[tt] = 0.f;
    for (int k = 0; k < IN_DIM; k++) {
        float w = __ldg(&win[k * H + j]);
#pragma unroll
        for (int tt = 0; tt < TCH; tt++) acc[tt] += xs[tt][k] * w;
    }
#pragma unroll
    for (int tt = 0; tt < TCH; tt++) g_IIN[(t0 + tt) * H + j] = acc[tt];
}

// ---------------- persistent reservoir kernel --------------------------------
__global__ void __launch_bounds__(TPB, 1) reservoir_kernel(
    const float* __restrict__ W,    // recurrent weights [H,H]
    const float* __restrict__ Rw,   // readout weights   [H,OUT]
    const float* __restrict__ Rb,   // readout bias      [OUT]
    float* __restrict__ out)        // [OUT]
{
    __shared__ int   s_spk[H];              // 16 KB spike list copy
    __shared__ int   s_cnt[NSEG];
    __shared__ float s_acc[9 * TPB];        // 18 KB delay accumulators (conflict-free)
    __shared__ unsigned s_wm[TPB / 32];

    const int tid  = threadIdx.x;
    const int b    = blockIdx.x;
    const int gtid = b * TPB + tid;
    const bool isA = (b < NSEG);            // phase-A (state-owner) blocks
    const int  g   = b >> 3;                // group 0..17
    const int  col = ((b & 7) << 9) + tid;  // owned column 0..4095
    const int  j   = gtid;                  // owned neuron (phase A)

    // ---- init: zero partial future buffers (exactly 10 iters/thread) ----
    for (int i = gtid; i < NGRP * ND * H; i += NB * TPB)
        __stcg(&((float*)g_Fp)[i], 0.f);

    float v = 0.f, gam = 1.f, rate = 0.f, vsum = 0.f;
    grid_sync();

    for (int t = 0; t < NSTEPS; t++) {
        const int slot = t % ND;

        // ================= Phase A: neuron update + spike compaction =========
        if (isA) {
            float irec = 0.f;
#pragma unroll
            for (int gg = 0; gg < NGRP; gg++) {
                float* p = &g_Fp[gg][slot][j];
                irec += __ldcg(p);
                __stcg(p, 0.f);             // clear consumed slot
            }
            float iin  = g_IIN[t * H + j];
            // match reference's non-fused mul/add in the threshold path
            float itot = __fmul_rn(__fadd_rn(iin, irec), gam);
            v = __fadd_rn(__fmul_rn(v, DECAY_F), itot);
            bool sp = (v >= 1.0f);
            if (sp) v = 0.f;
            float spf = sp ? 1.f : 0.f;
            rate = __fadd_rn(__fmul_rn(0.9f, rate), __fmul_rn(0.1f, spf));
            gam  = __fadd_rn(gam, __fmul_rn(0.01f, __fadd_rn(0.1f, -rate)));
            gam  = fminf(fmaxf(gam, 0.5f), 2.0f);
            vsum += v;

            // deterministic intra-block compaction
            unsigned m = __ballot_sync(0xffffffffu, sp);
            int lane = tid & 31, wid = tid >> 5;
            if (lane == 0) s_wm[wid] = m;
            __syncthreads();
            int base = 0;
#pragma unroll
            for (int w2 = 0; w2 < TPB / 32; w2++)
                if (w2 < wid) base += __popc(s_wm[w2]);
            int pos = base + __popc(m & ((1u << lane) - 1u));
            if (sp) __stcg(&g_spk[b * TPB + pos], j);
            if (tid == TPB - 1) __stcg(&g_cnt[b], base + __popc(m));
        }
        grid_sync();   // spike list complete; F slot-t clears done

        // ================= Phase B: event-driven scatter =====================
        if (tid < NSEG) s_cnt[tid] = __ldcg(&g_cnt[tid]);
        __syncthreads();
#pragma unroll
        for (int d = 0; d < 9; d++) s_acc[d * TPB + tid] = 0.f;
        for (int seg = 0; seg < NSEG; seg++) {
            int c = s_cnt[seg];
            for (int k2 = tid; k2 < c; k2 += TPB)
                s_spk[seg * TPB + k2] = __ldcg(&g_spk[seg * TPB + k2]);
        }
        __syncthreads();

        for (int seg = 0; seg < NSEG; seg++) {
            const int  c  = s_cnt[seg];
            const int* sl = &s_spk[seg * TPB];
#pragma unroll 4
            for (int k = g; k < c; k += NGRP) {
                int i   = sl[k];                      // block-uniform (broadcast LDS)
                int off = (i << 12) + col;            // i*H + col, fits int32
                float w = __ldg(W + off);
                int   d = (int)__ldg(g_DPK + off);    // 1..9
                s_acc[((d - 1) << 9) + tid] += w;     // conflict-free smem accumulate
            }
        }

        // flush to exclusive partial slots (deterministic, no atomics)
#pragma unroll
        for (int d = 1; d <= 9; d++) {
            float a = s_acc[((d - 1) << 9) + tid];
            float* p = &g_Fp[g][(slot + d) % ND][col];
            __stcg(p, __ldcg(p) + a);
        }
        grid_sync();   // F ready for next phase A
    }

    // ---- epilogue: vsum -> global, then block 0 computes readout ----
    if (isA) __stcg(&g_vsum[j], vsum);
    grid_sync();

    if (b == 0) {
        int o = tid & 63, q = tid >> 6;               // 8 partials per output
        float s = 0.f;
        for (int jj = q * 512; jj < q * 512 + 512; jj++) {
            float vm = __ldcg(&g_vsum[jj]) / 100.0f;  // match vs.mean(0) rounding
            s += vm * __ldg(&Rw[jj * OUT_DIM + o]);
        }
        s_acc[tid] = s;
        __syncthreads();
        if (tid < OUT_DIM) {
            float tot = 0.f;
#pragma unroll
            for (int q2 = 0; q2 < 8; q2++) tot += s_acc[q2 * 64 + tid];
            out[tid] = tot + __ldg(&Rb[tid]);
        }
    }
}

// ---------------- host launch -------------------------------------------------
extern "C" void kernel_launch(void* const* d_in, const int* in_sizes, int n_in,
                              void* d_out, int out_size) {
    const float* x      = (const float*)d_in[0];   // [100,512]
    const float* win    = (const float*)d_in[1];   // [512,4096]
    const float* W      = (const float*)d_in[2];   // [4096,4096]
    const float* Rw     = (const float*)d_in[3];   // [4096,64]
    const float* Rb     = (const float*)d_in[4];   // [64]
    const int*   delays = (const int*)d_in[5];     // [4096,4096]
    (void)in_sizes; (void)n_in; (void)out_size;

    pack_kernel<<<(H * H / 4) / 256, 256>>>(delays);
    dim3 gg(H / 256, NSTEPS / TCH);
    iin_kernel<<<gg, 256>>>(x, win);
    reservoir_kernel<<<NB, TPB>>>(W, Rw, Rb, (float*)d_out);
}

// round 6
// speedup vs baseline: 1.2185x; 1.2185x over previous
#include <cuda_runtime.h>
#include <cuda_bf16.h>
#include <cstdint>

#define H        4096
#define NSTEPS   100
#define IN_DIM   512
#define OUT_DIM  64
#define ND       10          // delay ring slots
#define NB       144         // persistent blocks, 1/SM (<=148 -> co-resident)
#define TPB      1024        // 32 warps/SM -> 8 warps/SMSP
#define NGRP     36          // NB/4 scatter groups
#define NSEG     4           // phase-A blocks (4 x 1024 neurons)
#define DECAY_F  0.9512294245007141f

// ---------------- static device state (no runtime allocation) ----------------
__device__ float          g_Fp[NB][ND][TPB];       // per-block partial future currents (5.9 MB)
__device__ float          g_IIN[NSTEPS * H];       // precomputed input currents
__device__ unsigned char  g_DPK[(size_t)H * H];    // packed delays 1..9 (16 MB)
__device__ unsigned short g_spk[H];                // segmented compacted spike list
__device__ int            g_cnt[NSEG];
__device__ float          g_vsum[H];
__device__ unsigned       g_barA = 0u;
__device__ unsigned       g_barG = 0u;

// ---------------- manual grid barrier ----------------------------------------
__device__ __forceinline__ void grid_sync() {
    __threadfence();
    __syncthreads();
    if (threadIdx.x == 0) {
        unsigned gen = *((volatile unsigned*)&g_barG);
        unsigned a = atomicAdd(&g_barA, 1u);
        if (a == NB - 1u) {
            g_barA = 0u;
            __threadfence();
            atomicAdd(&g_barG, 1u);
        } else {
            while (*((volatile unsigned*)&g_barG) == gen) { }
        }
        __threadfence();
    }
    __syncthreads();
}

// ---------------- pre-pass 1: pack int32 delays -> uint8 ---------------------
__global__ void __launch_bounds__(256) pack_kernel(const int* __restrict__ delays) {
    int idx = blockIdx.x * 256 + threadIdx.x;        // H*H/4 iters
    int4 d = ((const int4*)delays)[idx];
    uchar4 p;
    p.x = (unsigned char)d.x; p.y = (unsigned char)d.y;
    p.z = (unsigned char)d.z; p.w = (unsigned char)d.w;
    ((uchar4*)g_DPK)[idx] = p;
}

// ---------------- pre-pass 2: input currents IIN = X @ Win -------------------
#define TCH 10
__global__ void __launch_bounds__(256) iin_kernel(const float* __restrict__ x,
                                                  const float* __restrict__ win) {
    __shared__ float xs[TCH][IN_DIM];
    int j  = blockIdx.x * 256 + threadIdx.x;
    int t0 = blockIdx.y * TCH;
    for (int idx = threadIdx.x; idx < TCH * IN_DIM; idx += 256)
        xs[idx >> 9][idx & 511] = x[(t0 + (idx >> 9)) * IN_DIM + (idx & 511)];
    __syncthreads();
    float acc[TCH];
#pragma unroll
    for (int tt = 0; tt < TCH; tt++) acc[tt] = 0.f;
    for (int k = 0; k < IN_DIM; k++) {
        float w = __ldg(&win[k * H + j]);
#pragma unroll
        for (int tt = 0; tt < TCH; tt++) acc[tt] += xs[tt][k] * w;
    }
#pragma unroll
    for (int tt = 0; tt < TCH; tt++) g_IIN[(t0 + tt) * H + j] = acc[tt];
}

// ---------------- persistent reservoir kernel --------------------------------
__global__ void __launch_bounds__(TPB, 1) reservoir_kernel(
    const float* __restrict__ W,    // [H,H]
    const float* __restrict__ Rw,   // [H,OUT]
    const float* __restrict__ Rb,   // [OUT]
    float* __restrict__ out)        // [OUT]
{
    __shared__ unsigned short s_spk[NSEG * TPB];   // 8 KB spike list
    __shared__ float s_acc[9 * TPB];               // 36 KB delay accumulators
    __shared__ int   s_cnt[NSEG];
    __shared__ unsigned s_wm[TPB / 32];

    const int tid  = threadIdx.x;
    const int b    = blockIdx.x;
    const int gtid = b * TPB + tid;
    const bool isA = (b < NSEG);
    const int  span = b & 3;               // column span 0..3 (1024 cols each)
    const int  grp  = b >> 2;              // scatter group 0..35
    const int  col  = (span << 10) + tid;  // owned column
    const int  j    = (b << 10) + tid;     // owned neuron (phase A only, b<4)
    const float* Wc = W + col;             // hoisted column bases
    const unsigned char* Dc = g_DPK + col;

    // zero partial future buffers (NB*ND*TPB floats, 10 iters/thread)
    for (int i = gtid; i < NB * ND * TPB; i += NB * TPB)
        __stcg(&((float*)g_Fp)[i], 0.f);

    float v = 0.f, gam = 1.f, rate = 0.f, vsum = 0.f;
    grid_sync();

    for (int t = 0; t < NSTEPS; t++) {
        const int slot = t % ND;

        // ================= Phase A: LIF update + spike compaction ===========
        if (isA) {
            float irec = 0.f;
#pragma unroll
            for (int g2 = 0; g2 < NGRP; g2++) {
                float* p = &g_Fp[(g2 << 2) + b][slot][tid];   // span=b, local col=tid
                irec += __ldcg(p);
                __stcg(p, 0.f);
            }
            float iin  = g_IIN[t * H + j];
            float itot = __fmul_rn(__fadd_rn(iin, irec), gam);
            v = __fadd_rn(__fmul_rn(v, DECAY_F), itot);
            bool sp = (v >= 1.0f);
            if (sp) v = 0.f;
            float spf = sp ? 1.f : 0.f;
            rate = __fadd_rn(__fmul_rn(0.9f, rate), __fmul_rn(0.1f, spf));
            gam  = __fadd_rn(gam, __fmul_rn(0.01f, __fadd_rn(0.1f, -rate)));
            gam  = fminf(fmaxf(gam, 0.5f), 2.0f);
            vsum += v;

            unsigned m = __ballot_sync(0xffffffffu, sp);
            int lane = tid & 31, wid = tid >> 5;
            if (lane == 0) s_wm[wid] = m;
            __syncthreads();
            int base = 0;
#pragma unroll
            for (int w2 = 0; w2 < TPB / 32; w2++)
                if (w2 < wid) base += __popc(s_wm[w2]);
            int pos = base + __popc(m & ((1u << lane) - 1u));
            if (sp) __stcg(&g_spk[(b << 10) + pos], (unsigned short)j);
            if (tid == TPB - 1) __stcg(&g_cnt[b], base + __popc(m));
        }
        grid_sync();   // spike list ready; slot-t partials cleared

        // ================= Phase B: event-driven scatter ====================
        if (tid < NSEG) s_cnt[tid] = __ldcg(&g_cnt[tid]);
        __syncthreads();
#pragma unroll
        for (int d = 0; d < 9; d++) s_acc[(d << 10) + tid] = 0.f;
        for (int seg = 0; seg < NSEG; seg++) {
            int c = s_cnt[seg];
            for (int k2 = tid; k2 < c; k2 += TPB)
                s_spk[(seg << 10) + k2] = __ldcg(&g_spk[(seg << 10) + k2]);
        }
        __syncthreads();

        for (int seg = 0; seg < NSEG; seg++) {
            const int c = s_cnt[seg];
            const unsigned short* sl = &s_spk[seg << 10];
#pragma unroll 4
            for (int k = grp; k < c; k += NGRP) {
                int row = ((int)sl[k]) << 12;          // block-uniform broadcast
                float w = __ldcg(Wc + row);            // no reuse -> skip L1
                int   d = (int)__ldg(Dc + row);        // L1: line serves 4 warps
                // thread-exclusive address -> deterministic, no dependency chain
                atomicAdd(&s_acc[((d - 1) << 10) + tid], w);
            }
        }
        __syncthreads();   // all atomics of this block done before flush reads

        // flush to this block's exclusive partial slots
#pragma unroll
        for (int d = 1; d <= 9; d++) {
            int s = slot + d; if (s >= ND) s -= ND;
            float a = s_acc[((d - 1) << 10) + tid];
            float* p = &g_Fp[b][s][tid];
            __stcg(p, __ldcg(p) + a);
        }
        grid_sync();   // future currents visible for next phase A
    }

    // ---- epilogue: readout ----
    if (isA) __stcg(&g_vsum[j], vsum);
    grid_sync();

    if (b == 0) {
        int o = tid & 63, q = tid >> 6;               // 16 partials per output
        float s = 0.f;
        for (int jj = q * 256; jj < q * 256 + 256; jj++) {
            float vm = __ldcg(&g_vsum[jj]) / 100.0f;
            s += vm * __ldg(&Rw[jj * OUT_DIM + o]);
        }
        s_acc[tid] = s;
        __syncthreads();
        if (tid < OUT_DIM) {
            float tot = 0.f;
#pragma unroll
            for (int q2 = 0; q2 < 16; q2++) tot += s_acc[q2 * 64 + tid];
            out[tid] = tot + __ldg(&Rb[tid]);
        }
    }
}

// ---------------- host launch -------------------------------------------------
extern "C" void kernel_launch(void* const* d_in, const int* in_sizes, int n_in,
                              void* d_out, int out_size) {
    const float* x      = (const float*)d_in[0];   // [100,512]
    const float* win    = (const float*)d_in[1];   // [512,4096]
    const float* W      = (const float*)d_in[2];   // [4096,4096]
    const float* Rw     = (const float*)d_in[3];   // [4096,64]
    const float* Rb     = (const float*)d_in[4];   // [64]
    const int*   delays = (const int*)d_in[5];     // [4096,4096]
    (void)in_sizes; (void)n_in; (void)out_size;

    pack_kernel<<<(H * H / 4) / 256, 256>>>(delays);
    dim3 gg(H / 256, NSTEPS / TCH);
    iin_kernel<<<gg, 256>>>(x, win);
    reservoir_kernel<<<NB, TPB>>>(W, Rw, Rb, (float*)d_out);
}

// round 7
// speedup vs baseline: 1.5274x; 1.2536x over previous
#include <cuda_runtime.h>
#include <cuda_bf16.h>
#include <cstdint>

#define H        4096
#define NSTEPS   100
#define IN_DIM   512
#define OUT_DIM  64
#define ND       10          // delay ring slots
#define NB       144         // persistent blocks, 1/SM (co-resident, proven)
#define TPB      1024        // 32 warps/SM
#define NGRP     36          // scatter groups (NB/4)
#define NSEGA    128         // phase-A blocks, 32 neurons (1 warp) each
#define DECAY_F  0.9512294245007141f

// ---------------- static device state ----------------------------------------
__device__ float          g_Fp[NGRP][ND][H];       // partial future currents (5.9 MB)
__device__ float          g_IIN[NSTEPS * H];       // precomputed input currents
__device__ unsigned char  g_DPK[(size_t)H * H];    // packed delays 1..9 (16 MB)
__device__ unsigned short g_spk[H];                // segmented spike list (128 segs x 32)
__device__ int            g_cnt[NSEGA];
__device__ float          g_vsum[H];
__device__ unsigned       g_barA = 0u;
__device__ unsigned       g_barG = 0u;

// ---------------- manual grid barrier (proven in R4/R6) -----------------------
__device__ __forceinline__ void grid_sync() {
    __threadfence();
    __syncthreads();
    if (threadIdx.x == 0) {
        unsigned gen = *((volatile unsigned*)&g_barG);
        unsigned a = atomicAdd(&g_barA, 1u);
        if (a == NB - 1u) {
            g_barA = 0u;
            __threadfence();
            atomicAdd(&g_barG, 1u);
        } else {
            while (*((volatile unsigned*)&g_barG) == gen) { }
        }
        __threadfence();
    }
    __syncthreads();
}

// ---------------- pre-pass 1: pack int32 delays -> uint8 ----------------------
__global__ void __launch_bounds__(256) pack_kernel(const int* __restrict__ delays) {
    int idx = blockIdx.x * 256 + threadIdx.x;        // H*H/4 iters
    int4 d = ((const int4*)delays)[idx];
    uchar4 p;
    p.x = (unsigned char)d.x; p.y = (unsigned char)d.y;
    p.z = (unsigned char)d.z; p.w = (unsigned char)d.w;
    ((uchar4*)g_DPK)[idx] = p;
}

// ---------------- pre-pass 2: input currents IIN = X @ Win --------------------
#define TCH 10
__global__ void __launch_bounds__(256) iin_kernel(const float* __restrict__ x,
                                                  const float* __restrict__ win) {
    __shared__ float xs[TCH][IN_DIM];
    int j  = blockIdx.x * 256 + threadIdx.x;
    int t0 = blockIdx.y * TCH;
    for (int idx = threadIdx.x; idx < TCH * IN_DIM; idx += 256)
        xs[idx >> 9][idx & 511] = x[(t0 + (idx >> 9)) * IN_DIM + (idx & 511)];
    __syncthreads();
    float acc[TCH];
#pragma unroll
    for (int tt = 0; tt < TCH; tt++) acc[tt] = 0.f;
    for (int k = 0; k < IN_DIM; k++) {
        float w = __ldg(&win[k * H + j]);
#pragma unroll
        for (int tt = 0; tt < TCH; tt++) acc[tt] += xs[tt][k] * w;
    }
#pragma unroll
    for (int tt = 0; tt < TCH; tt++) g_IIN[(t0 + tt) * H + j] = acc[tt];
}

// ---------------- persistent reservoir kernel ---------------------------------
__global__ void __launch_bounds__(TPB, 1) reservoir_kernel(
    const float* __restrict__ W,    // [H,H]
    const float* __restrict__ Rw,   // [H,OUT]
    const float* __restrict__ Rb,   // [OUT]
    float* __restrict__ out)        // [OUT]
{
    __shared__ unsigned short s_dense[H];   // 8 KB dense spike list
    __shared__ int   s_cnt[NSEGA];
    __shared__ int   s_off[NSEGA];
    __shared__ int   s_ns;
    __shared__ float s_red[TPB];            // readout partials (epilogue only)

    const int tid  = threadIdx.x;
    const int b    = blockIdx.x;
    const int gtid = b * TPB + tid;
    const int lane = tid & 31;
    const bool isA = (b < NSEGA) && (tid < 32);   // phase-A: 1 warp x 32 neurons
    const int  span = b & 3;                // column span 0..3
    const int  grp  = b >> 2;               // scatter group 0..35
    const int  col  = (span << 10) + tid;   // owned column 0..4095
    const int  j    = (b << 5) + lane;      // owned neuron (phase A only)
    const float* Wc = W + col;
    const unsigned char* Dc = g_DPK + col;

    // zero partial future buffers (10 iters/thread)
    for (int i = gtid; i < NGRP * ND * H; i += NB * TPB)
        __stcg(&((float*)g_Fp)[i], 0.f);

    float v = 0.f, gam = 1.f, rate = 0.f, vsum = 0.f;
    grid_sync();

    for (int t = 0; t < NSTEPS; t++) {
        const int slot = t % ND;

        // ============ Phase A: LIF update + warp-local spike compaction ======
        if (isA) {
            float irec = 0.f;
#pragma unroll
            for (int g2 = 0; g2 < NGRP; g2++) {
                float* p = &g_Fp[g2][slot][j];
                irec += __ldcg(p);
                __stcg(p, 0.f);
            }
            float iin  = g_IIN[t * H + j];
            float itot = __fmul_rn(__fadd_rn(iin, irec), gam);
            v = __fadd_rn(__fmul_rn(v, DECAY_F), itot);
            bool sp = (v >= 1.0f);
            if (sp) v = 0.f;
            float spf = sp ? 1.f : 0.f;
            rate = __fadd_rn(__fmul_rn(0.9f, rate), __fmul_rn(0.1f, spf));
            gam  = __fadd_rn(gam, __fmul_rn(0.01f, __fadd_rn(0.1f, -rate)));
            gam  = fminf(fmaxf(gam, 0.5f), 2.0f);
            vsum += v;

            unsigned m = __ballot_sync(0xffffffffu, sp);
            int pos = __popc(m & ((1u << lane) - 1u));
            if (sp) __stcg(&g_spk[(b << 5) + pos], (unsigned short)j);
            if (lane == 0) __stcg(&g_cnt[b], __popc(m));
        }
        grid_sync();   // spike segments ready; slot-t partials cleared

        // ============ Phase B: build dense list, then scatter ================
        if (tid < NSEGA) s_cnt[tid] = __ldcg(&g_cnt[tid]);
        __syncthreads();
        if (tid < 32) {           // warp 0: shfl-scan 128 counts -> offsets
            int c0 = s_cnt[4*tid+0], c1 = s_cnt[4*tid+1];
            int c2 = s_cnt[4*tid+2], c3 = s_cnt[4*tid+3];
            int s  = c0 + c1 + c2 + c3;
            int inc = s;
#pragma unroll
            for (int o = 1; o < 32; o <<= 1) {
                int nv = __shfl_up_sync(0xffffffffu, inc, o);
                if (tid >= o) inc += nv;
            }
            int excl = inc - s;
            s_off[4*tid+0] = excl;
            s_off[4*tid+1] = excl + c0;
            s_off[4*tid+2] = excl + c0 + c1;
            s_off[4*tid+3] = excl + c0 + c1 + c2;
            if (tid == 31) s_ns = inc;
        }
        __syncthreads();
        if (tid < NSEGA) {        // copy segments to dense positions
            int c = s_cnt[tid], o = s_off[tid];
            const unsigned short* sb = &g_spk[tid << 5];
            for (int k = 0; k < c; k++) s_dense[o + k] = __ldcg(sb + k);
        }
        __syncthreads();

        // register delay accumulators: no smem RMW, no ATOMS pipe
        float acc[9];
#pragma unroll
        for (int d = 0; d < 9; d++) acc[d] = 0.f;
        const int ns = s_ns;
        for (int k = grp; k < ns; k += NGRP) {
            int row = ((int)s_dense[k]) << 12;   // block-uniform broadcast LDS
            float w = __ldcg(Wc + row);          // zero reuse -> bypass L1
            int   d = (int)__ldg(Dc + row);      // L1: line shared by block's warps
#pragma unroll
            for (int ii = 0; ii < 9; ii++)       // branch-free select-add
                acc[ii] += (d == ii + 1) ? w : 0.f;
        }

        // flush to this group's exclusive partial slots (deterministic)
#pragma unroll
        for (int d = 1; d <= 9; d++) {
            int s = slot + d; if (s >= ND) s -= ND;
            float* p = &g_Fp[grp][s][col];
            __stcg(p, __ldcg(p) + acc[d - 1]);
        }
        grid_sync();   // future currents visible for next phase A
    }

    // ---- epilogue: readout ----
    if (isA) __stcg(&g_vsum[j], vsum);
    grid_sync();

    if (b == 0) {
        int o = tid & 63, q = tid >> 6;          // 16 partials per output
        float s = 0.f;
        for (int jj = q * 256; jj < q * 256 + 256; jj++) {
            float vm = __ldcg(&g_vsum[jj]) / 100.0f;
            s += vm * __ldg(&Rw[jj * OUT_DIM + o]);
        }
        s_red[tid] = s;
        __syncthreads();
        if (tid < OUT_DIM) {
            float tot = 0.f;
#pragma unroll
            for (int q2 = 0; q2 < 16; q2++) tot += s_red[q2 * 64 + tid];
            out[tid] = tot + __ldg(&Rb[tid]);
        }
    }
}

// ---------------- host launch --------------------------------------------------
extern "C" void kernel_launch(void* const* d_in, const int* in_sizes, int n_in,
                              void* d_out, int out_size) {
    const float* x      = (const float*)d_in[0];   // [100,512]
    const float* win    = (const float*)d_in[1];   // [512,4096]
    const float* W      = (const float*)d_in[2];   // [4096,4096]
    const float* Rw     = (const float*)d_in[3];   // [4096,64]
    const float* Rb     = (const float*)d_in[4];   // [64]
    const int*   delays = (const int*)d_in[5];     // [4096,4096]
    (void)in_sizes; (void)n_in; (void)out_size;

    pack_kernel<<<(H * H / 4) / 256, 256>>>(delays);
    dim3 gg(H / 256, NSTEPS / TCH);
    iin_kernel<<<gg, 256>>>(x, win);
    reservoir_kernel<<<NB, TPB>>>(W, Rw, Rb, (float*)d_out);
}

// round 8
// speedup vs baseline: 1.7442x; 1.1419x over previous
#include <cuda_runtime.h>
#include <cuda_bf16.h>
#include <cstdint>

#define H        4096
#define NSTEPS   100
#define IN_DIM   512
#define OUT_DIM  64
#define ND       10
#define NB       144          // persistent blocks, 1/SM, co-resident (proven)
#define TPB      1024
#define NGRP     72           // scatter groups: grp = b>>1, 2048 cols each
#define NSEGA    128          // phase-A warps (32 neurons each)
#define DECAY_F  0.9512294245007141f
typedef unsigned long long ull;

// ---------------- static device state ----------------------------------------
__device__ float          g_Fp[NGRP][ND][H];           // partial future currents (11.8 MB)
__device__ float          g_IIN[NSTEPS * H];           // input currents
__device__ unsigned char  g_DPK4[(size_t)H * H / 2];   // nibble-packed delays (8 MB)
__device__ unsigned short g_spk[H];
__device__ int            g_cnt[NSEGA];
__device__ float          g_vsum[H];
__device__ unsigned       g_barA = 0u;
__device__ unsigned       g_barG = 0u;

// ---------------- manual grid barrier (proven) --------------------------------
__device__ __forceinline__ void grid_sync() {
    __threadfence();
    __syncthreads();
    if (threadIdx.x == 0) {
        unsigned gen = *((volatile unsigned*)&g_barG);
        unsigned a = atomicAdd(&g_barA, 1u);
        if (a == NB - 1u) {
            g_barA = 0u;
            __threadfence();
            atomicAdd(&g_barG, 1u);
        } else {
            while (*((volatile unsigned*)&g_barG) == gen) { }
        }
        __threadfence();
    }
    __syncthreads();
}

// ---------------- single fused persistent kernel ------------------------------
__global__ void __launch_bounds__(TPB, 1) reservoir_kernel(
    const float* __restrict__ x,      // [100,512]
    const float* __restrict__ win,    // [512,4096]
    const float* __restrict__ W,      // [4096,4096]
    const float* __restrict__ Rw,     // [4096,64]
    const float* __restrict__ Rb,     // [64]
    const int*   __restrict__ delays, // [4096,4096]
    float* __restrict__ out)          // [64]
{
    __shared__ unsigned short s_dense[H];   // 8 KB dense spike list
    __shared__ int   s_cnt[NSEGA];
    __shared__ int   s_off[NSEGA];
    __shared__ int   s_ns;
    __shared__ float s_buf[10 * IN_DIM];    // 20 KB: x-tile (prologue) / readout (epilogue)

    const int tid  = threadIdx.x;
    const int b    = blockIdx.x;
    const int gtid = b * TPB + tid;
    const int lane = tid & 31;
    const bool isA = (b < NSEGA) && (tid < 32);
    const int  grp   = b >> 1;                    // 0..71
    const int  span  = b & 1;                     // 0..1
    const int  cpair = (span << 10) + tid;        // column-pair index 0..2047
    const int  jA    = (b << 5) + lane;           // phase-A neuron

    // ---- prologue part 1: zero partial future buffers (20 iters/thread) ----
    for (int i = gtid; i < NGRP * ND * H; i += NB * TPB)
        ((float*)g_Fp)[i] = 0.f;

    // ---- prologue part 2: specialize ----
    if (b < 40) {
        // input GEMM: block handles 10 steps x 1024 columns
        int t0 = (b >> 2) * 10;
        int j  = ((b & 3) << 10) + tid;
        for (int idx = tid; idx < 10 * IN_DIM; idx += TPB)
            s_buf[idx] = x[t0 * IN_DIM + idx];
        __syncthreads();
        float a[10];
#pragma unroll
        for (int tt = 0; tt < 10; tt++) a[tt] = 0.f;
        for (int k = 0; k < IN_DIM; k++) {
            float w = __ldg(&win[k * H + j]);
#pragma unroll
            for (int tt = 0; tt < 10; tt++) a[tt] += s_buf[tt * IN_DIM + k] * w;
        }
#pragma unroll
        for (int tt = 0; tt < 10; tt++) g_IIN[(t0 + tt) * H + j] = a[tt];
    } else {
        // nibble-pack delays: 16 ints -> one u64 (10 iters/thread)
        const int4* dl = (const int4*)delays;
        for (int idx = (b - 40) * TPB + tid; idx < H * H / 16; idx += 104 * TPB) {
            int4 a0 = dl[(idx << 2) + 0], a1 = dl[(idx << 2) + 1];
            int4 a2 = dl[(idx << 2) + 2], a3 = dl[(idx << 2) + 3];
            ull v = (ull)(a0.x & 15)       | ((ull)(a0.y & 15) << 4)
                  | ((ull)(a0.z & 15) << 8)  | ((ull)(a0.w & 15) << 12)
                  | ((ull)(a1.x & 15) << 16) | ((ull)(a1.y & 15) << 20)
                  | ((ull)(a1.z & 15) << 24) | ((ull)(a1.w & 15) << 28)
                  | ((ull)(a2.x & 15) << 32) | ((ull)(a2.y & 15) << 36)
                  | ((ull)(a2.z & 15) << 40) | ((ull)(a2.w & 15) << 44)
                  | ((ull)(a3.x & 15) << 48) | ((ull)(a3.y & 15) << 52)
                  | ((ull)(a3.z & 15) << 56) | ((ull)(a3.w & 15) << 60);
            ((ull*)g_DPK4)[idx] = v;
        }
    }

    float v = 0.f, gam = 1.f, rate = 0.f, vsum = 0.f;
    grid_sync();

    const float2* W2 = (const float2*)W;
    float2* Fp2 = (float2*)g_Fp;

    for (int t = 0; t < NSTEPS; t++) {
        const int slot = t % ND;

        // ============ Phase A: LIF update + warp-local compaction ===========
        if (isA) {
            float irec = 0.f;
#pragma unroll
            for (int g2 = 0; g2 < NGRP; g2++) {
                float* p = &g_Fp[g2][slot][jA];
                irec += __ldcg(p);
                __stcg(p, 0.f);
            }
            float iin  = g_IIN[t * H + jA];
            float itot = __fmul_rn(__fadd_rn(iin, irec), gam);
            v = __fadd_rn(__fmul_rn(v, DECAY_F), itot);
            bool sp = (v >= 1.0f);
            if (sp) v = 0.f;
            float spf = sp ? 1.f : 0.f;
            rate = __fadd_rn(__fmul_rn(0.9f, rate), __fmul_rn(0.1f, spf));
            gam  = __fadd_rn(gam, __fmul_rn(0.01f, __fadd_rn(0.1f, -rate)));
            gam  = fminf(fmaxf(gam, 0.5f), 2.0f);
            vsum += v;

            unsigned m = __ballot_sync(0xffffffffu, sp);
            int pos = __popc(m & ((1u << lane) - 1u));
            if (sp) __stcg(&g_spk[(b << 5) + pos], (unsigned short)jA);
            if (lane == 0) __stcg(&g_cnt[b], __popc(m));
        }
        grid_sync();

        // ============ Phase B: dense list build + scatter ====================
        if (tid < NSEGA) s_cnt[tid] = __ldcg(&g_cnt[tid]);
        __syncthreads();
        if (tid < 32) {                       // warp 0: scan 128 counts
            int c0 = s_cnt[4*tid+0], c1 = s_cnt[4*tid+1];
            int c2 = s_cnt[4*tid+2], c3 = s_cnt[4*tid+3];
            int s  = c0 + c1 + c2 + c3;
            int inc = s;
#pragma unroll
            for (int o = 1; o < 32; o <<= 1) {
                int nv = __shfl_up_sync(0xffffffffu, inc, o);
                if (tid >= o) inc += nv;
            }
            int excl = inc - s;
            s_off[4*tid+0] = excl;
            s_off[4*tid+1] = excl + c0;
            s_off[4*tid+2] = excl + c0 + c1;
            s_off[4*tid+3] = excl + c0 + c1 + c2;
            if (tid == 31) s_ns = inc;
        }
        __syncthreads();
        if (tid < NSEGA) {
            int c = s_cnt[tid], o = s_off[tid];
            const unsigned short* sb = &g_spk[tid << 5];
            for (int k = 0; k < c; k++) s_dense[o + k] = __ldcg(sb + k);
        }
        __syncthreads();

        float acc0[9], acc1[9];
#pragma unroll
        for (int d = 0; d < 9; d++) { acc0[d] = 0.f; acc1[d] = 0.f; }
        const int ns = s_ns;

        int k = grp;
        // ---- 4x unrolled: batch loads for MLP ----
        for (; k + 3 * NGRP < ns; k += 4 * NGRP) {
            int r0 = (((int)s_dense[k])            << 11) + cpair;
            int r1 = (((int)s_dense[k +     NGRP]) << 11) + cpair;
            int r2 = (((int)s_dense[k + 2 * NGRP]) << 11) + cpair;
            int r3 = (((int)s_dense[k + 3 * NGRP]) << 11) + cpair;
            float2 w0 = __ldcg(&W2[r0]);
            float2 w1 = __ldcg(&W2[r1]);
            float2 w2 = __ldcg(&W2[r2]);
            float2 w3 = __ldcg(&W2[r3]);
            int p0 = (int)__ldg(&g_DPK4[r0]);
            int p1 = (int)__ldg(&g_DPK4[r1]);
            int p2 = (int)__ldg(&g_DPK4[r2]);
            int p3 = (int)__ldg(&g_DPK4[r3]);
            int a0 = p0 & 15, b0 = p0 >> 4;
            int a1 = p1 & 15, b1 = p1 >> 4;
            int a2 = p2 & 15, b2 = p2 >> 4;
            int a3 = p3 & 15, b3 = p3 >> 4;
#pragma unroll
            for (int ii = 1; ii <= 9; ii++) {
                if (a0 == ii) acc0[ii-1] += w0.x;
                if (b0 == ii) acc1[ii-1] += w0.y;
                if (a1 == ii) acc0[ii-1] += w1.x;
                if (b1 == ii) acc1[ii-1] += w1.y;
                if (a2 == ii) acc0[ii-1] += w2.x;
                if (b2 == ii) acc1[ii-1] += w2.y;
                if (a3 == ii) acc0[ii-1] += w3.x;
                if (b3 == ii) acc1[ii-1] += w3.y;
            }
        }
        // ---- remainder ----
        for (; k < ns; k += NGRP) {
            int r0 = (((int)s_dense[k]) << 11) + cpair;
            float2 w0 = __ldcg(&W2[r0]);
            int p0 = (int)__ldg(&g_DPK4[r0]);
            int a0 = p0 & 15, b0 = p0 >> 4;
#pragma unroll
            for (int ii = 1; ii <= 9; ii++) {
                if (a0 == ii) acc0[ii-1] += w0.x;
                if (b0 == ii) acc1[ii-1] += w0.y;
            }
        }

        // ---- flush to this group's exclusive partial slots ----
#pragma unroll
        for (int d = 1; d <= 9; d++) {
            int s2 = slot + d; if (s2 >= ND) s2 -= ND;
            float2* p = &Fp2[(grp * ND + s2) * (H / 2) + cpair];
            float2 cur = __ldcg(p);
            cur.x += acc0[d - 1];
            cur.y += acc1[d - 1];
            __stcg(p, cur);
        }
        grid_sync();
    }

    // ---- epilogue: readout ----
    if (isA) __stcg(&g_vsum[jA], vsum);
    grid_sync();

    if (b == 0) {
        int o = tid & 63, q = tid >> 6;          // 16 partials per output
        float s = 0.f;
        for (int jj = q * 256; jj < q * 256 + 256; jj++) {
            float vm = __ldcg(&g_vsum[jj]) / 100.0f;
            s += vm * __ldg(&Rw[jj * OUT_DIM + o]);
        }
        s_buf[tid] = s;
        __syncthreads();
        if (tid < OUT_DIM) {
            float tot = 0.f;
#pragma unroll
            for (int q2 = 0; q2 < 16; q2++) tot += s_buf[q2 * 64 + tid];
            out[tid] = tot + __ldg(&Rb[tid]);
        }
    }
}

// ---------------- host launch: ONE kernel -------------------------------------
extern "C" void kernel_launch(void* const* d_in, const int* in_sizes, int n_in,
                              void* d_out, int out_size) {
    const float* x      = (const float*)d_in[0];
    const float* win    = (const float*)d_in[1];
    const float* W      = (const float*)d_in[2];
    const float* Rw     = (const float*)d_in[3];
    const float* Rb     = (const float*)d_in[4];
    const int*   delays = (const int*)d_in[5];
    (void)in_sizes; (void)n_in; (void)out_size;

    reservoir_kernel<<<NB, TPB>>>(x, win, W, Rw, Rb, delays, (float*)d_out);
}

// round 10
// speedup vs baseline: 2.3046x; 1.3213x over previous
#include <cuda_runtime.h>
#include <cuda_bf16.h>
#include <cstdint>

#define H        4096
#define NSTEPS   100
#define IN_DIM   512
#define OUT_DIM  64
#define ND       10
#define NBLK     128          // persistent blocks, block owns 32 cols + 32 neurons
#define TPB      1024
#define DECAY_F  0.9512294245007141f

// ---------------- static device state ----------------------------------------
__device__ float          g_IIN[NSTEPS * H];       // input currents (1.6 MB)
__device__ unsigned char  g_DPK[(size_t)H * H];    // byte delays 1..9 (16 MB)
__device__ unsigned short g_spk[2][H];             // parity-buffered spike segments
__device__ int            g_cnt[2][NBLK];
__device__ float          g_vsum[H];
__device__ unsigned       g_barA = 0u;
__device__ unsigned       g_barG = 0u;

// ---------------- grid barrier: fence only in tid 0 ---------------------------
__device__ __forceinline__ void grid_sync() {
    __syncthreads();
    if (threadIdx.x == 0) {
        __threadfence();                                  // release block's writes
        unsigned gen = *((volatile unsigned*)&g_barG);
        unsigned a = atomicAdd(&g_barA, 1u);
        if (a == NBLK - 1u) {
            g_barA = 0u;
            __threadfence();
            atomicAdd(&g_barG, 1u);
        } else {
            while (*((volatile unsigned*)&g_barG) == gen) { }
        }
        __threadfence();                                  // acquire
    }
    __syncthreads();
}

// ---------------- single fused persistent kernel ------------------------------
__global__ void __launch_bounds__(TPB, 1) reservoir_kernel(
    const float* __restrict__ x,      // [100,512]
    const float* __restrict__ win,    // [512,4096]
    const float* __restrict__ W,      // [4096,4096]
    const float* __restrict__ Rw,     // [4096,64]
    const float* __restrict__ Rb,     // [64]
    const int*   __restrict__ delays, // [4096,4096]
    float* __restrict__ out)          // [64]
{
    __shared__ float          s_acc[9 * 32 * 32];  // 36 KB [d][lane][w^lane]
    __shared__ unsigned short s_dense[H];          // 8 KB dense spike list
    __shared__ float          s_ring[ND][32];      // block-local delay ring
    __shared__ int            s_cnt[NBLK];
    __shared__ int            s_off[NBLK];
    __shared__ int            s_ns;

    const int tid  = threadIdx.x;
    const int b    = blockIdx.x;
    const int lane = tid & 31;
    const int wrp  = tid >> 5;
    const int col0 = b << 5;                 // this block's 32 columns / neurons

    // ---------------- prologue: input GEMM (blocks 0-39) / delay pack --------
    if (b < 40) {
        float* xs = s_acc;                   // reuse 20 KB
        int t0 = (b >> 2) * 10;
        int j  = ((b & 3) << 10) + tid;
        for (int idx = tid; idx < 10 * IN_DIM; idx += TPB)
            xs[idx] = x[t0 * IN_DIM + idx];
        __syncthreads();
        float a[10];
#pragma unroll
        for (int tt = 0; tt < 10; tt++) a[tt] = 0.f;
        for (int k = 0; k < IN_DIM; k++) {
            float wv = __ldg(&win[k * H + j]);
#pragma unroll
            for (int tt = 0; tt < 10; tt++) a[tt] += xs[tt * IN_DIM + k] * wv;
        }
#pragma unroll
        for (int tt = 0; tt < 10; tt++) g_IIN[(t0 + tt) * H + j] = a[tt];
        __syncthreads();                     // xs reads done before s_acc reuse
    } else {
        const int4* dl = (const int4*)delays;
        uchar4* dp = (uchar4*)g_DPK;
        for (int idx = (b - 40) * TPB + tid; idx < H * H / 4; idx += 88 * TPB) {
            int4 d4 = dl[idx];
            dp[idx] = make_uchar4((unsigned char)d4.x, (unsigned char)d4.y,
                                  (unsigned char)d4.z, (unsigned char)d4.w);
        }
    }
    if (tid < ND * 32) ((float*)s_ring)[tid] = 0.f;

    float v = 0.f, gam = 1.f, rate = 0.f, vsum = 0.f;

    // phase A for step t: warp 0 only, block's own 32 neurons, smem ring
    auto phaseA = [&](int t) {
        if (wrp == 0) {
            float irec = s_ring[t % ND][lane];
            s_ring[t % ND][lane] = 0.f;
            float iin  = g_IIN[t * H + col0 + lane];
            float itot = __fmul_rn(__fadd_rn(iin, irec), gam);
            v = __fadd_rn(__fmul_rn(v, DECAY_F), itot);
            bool sp = (v >= 1.0f);
            if (sp) v = 0.f;
            float spf = sp ? 1.f : 0.f;
            rate = __fadd_rn(__fmul_rn(0.9f, rate), __fmul_rn(0.1f, spf));
            gam  = __fadd_rn(gam, __fmul_rn(0.01f, __fadd_rn(0.1f, -rate)));
            gam  = fminf(fmaxf(gam, 0.5f), 2.0f);
            vsum += v;
            unsigned m = __ballot_sync(0xffffffffu, sp);
            int pos = __popc(m & ((1u << lane) - 1u));
            int par = t & 1;
            if (sp) __stcg(&g_spk[par][col0 + pos], (unsigned short)(col0 + lane));
            if (lane == 0) __stcg(&g_cnt[par][b], __popc(m));
        }
    };

    grid_sync();          // prologue data (IIN, DPK) visible everywhere
    phaseA(0);
    grid_sync();          // step-0 spike list published

    for (int t = 0; t < NSTEPS - 1; t++) {
        const int par  = t & 1;
        const int slot = t % ND;

        // ---- zero accumulators + fetch counts ----
#pragma unroll
        for (int i = tid; i < 9 * 32 * 32; i += TPB) s_acc[i] = 0.f;
        if (tid < NBLK) s_cnt[tid] = __ldcg(&g_cnt[par][tid]);
        __syncthreads();

        // ---- warp 0: scan 128 counts -> offsets ----
        if (tid < 32) {
            int c0 = s_cnt[4*tid+0], c1 = s_cnt[4*tid+1];
            int c2 = s_cnt[4*tid+2], c3 = s_cnt[4*tid+3];
            int s  = c0 + c1 + c2 + c3;
            int inc = s;
#pragma unroll
            for (int o = 1; o < 32; o <<= 1) {
                int nv = __shfl_up_sync(0xffffffffu, inc, o);
                if (tid >= o) inc += nv;
            }
            int ex = inc - s;
            s_off[4*tid+0] = ex;
            s_off[4*tid+1] = ex + c0;
            s_off[4*tid+2] = ex + c0 + c1;
            s_off[4*tid+3] = ex + c0 + c1 + c2;
            if (tid == 31) s_ns = inc;
        }
        __syncthreads();

        // ---- gather segments into dense list ----
        if (tid < NBLK) {
            int c = s_cnt[tid], o = s_off[tid];
            const unsigned short* sb = &g_spk[par][tid << 5];
            for (int k = 0; k < c; k++) s_dense[o + k] = __ldcg(sb + k);
        }
        __syncthreads();

        // ---- scatter: warp = spike, lane = column, 1 smem RMW per weight ----
        const int ns  = s_ns;
        const int swz = (lane << 5) + (wrp ^ lane);   // conflict-free slice
        int k = wrp;
        for (; k + 32 < ns; k += 64) {                // 2x unroll for MLP
            int r0 = ((int)s_dense[k])      << 12;
            int r1 = ((int)s_dense[k + 32]) << 12;
            float w0 = __ldcg(&W[r0 + col0 + lane]);  // coalesced 128B
            float w1 = __ldcg(&W[r1 + col0 + lane]);
            int d0 = (int)__ldg(&g_DPK[r0 + col0 + lane]);
            int d1 = (int)__ldg(&g_DPK[r1 + col0 + lane]);
            s_acc[((d0 - 1) << 10) + swz] += w0;
            s_acc[((d1 - 1) << 10) + swz] += w1;
        }
        for (; k < ns; k += 32) {
            int r0 = ((int)s_dense[k]) << 12;
            float w0 = __ldcg(&W[r0 + col0 + lane]);
            int d0 = (int)__ldg(&g_DPK[r0 + col0 + lane]);
            s_acc[((d0 - 1) << 10) + swz] += w0;
        }
        __syncthreads();

        // ---- reduce 32 warp-partials per (d, col) into the smem ring ----
        if (tid < 288) {
            int d = tid >> 5, l2 = tid & 31;          // d in 0..8 -> delay d+1
            const float* base = &s_acc[(d << 10) + (l2 << 5)];
            float s = 0.f;
#pragma unroll
            for (int ww = 0; ww < 32; ww++) s += base[ww ^ l2];
            int s2 = slot + d + 1;                    // slot-based: max 18
            if (s2 >= ND) s2 -= ND;                   // single wrap suffices
            s_ring[s2][l2] += s;
        }
        __syncthreads();

        // ---- next step's LIF + spike publish (opposite parity buffer) ----
        phaseA(t + 1);
        grid_sync();
    }

    // ---------------- epilogue: readout ----------------
    if (wrp == 0) __stcg(&g_vsum[col0 + lane], vsum);
    grid_sync();

    if (b == 0) {
        float* s_red = s_acc;
        int o = tid & 63, q = tid >> 6;               // 16 partials per output
        float s = 0.f;
        for (int jj = q * 256; jj < q * 256 + 256; jj++) {
            float vm = __ldcg(&g_vsum[jj]) / 100.0f;
            s += vm * __ldg(&Rw[jj * OUT_DIM + o]);
        }
        s_red[tid] = s;
        __syncthreads();
        if (tid < OUT_DIM) {
            float tot = 0.f;
#pragma unroll
            for (int q2 = 0; q2 < 16; q2++) tot += s_red[q2 * 64 + tid];
            out[tid] = tot + __ldg(&Rb[tid]);
        }
    }
}

// ---------------- host launch: ONE kernel -------------------------------------
extern "C" void kernel_launch(void* const* d_in, const int* in_sizes, int n_in,
                              void* d_out, int out_size) {
    const float* x      = (const float*)d_in[0];
    const float* win    = (const float*)d_in[1];
    const float* W      = (const float*)d_in[2];
    const float* Rw     = (const float*)d_in[3];
    const float* Rb     = (const float*)d_in[4];
    const int*   delays = (const int*)d_in[5];
    (void)in_sizes; (void)n_in; (void)out_size;

    reservoir_kernel<<<NBLK, TPB>>>(x, win, W, Rw, Rb, delays, (float*)d_out);
}

// round 12
// speedup vs baseline: 2.5787x; 1.1189x over previous
#include <cuda_runtime.h>
#include <cuda_bf16.h>
#include <cstdint>

#define H        4096
#define NSTEPS   100
#define IN_DIM   512
#define OUT_DIM  64
#define ND       10
#define NBLK     128          // persistent blocks; block owns 32 cols + 32 neurons
#define TPB      1024
#define DECAY_F  0.9512294245007141f

// ---------------- static device state ----------------------------------------
__device__ float          g_IIN[NSTEPS * H];       // input currents (1.6 MB)
__device__ unsigned char  g_DPK[(size_t)H * H];    // byte delays 1..9 (16 MB)
__device__ unsigned       g_mask[2][NBLK];         // parity-buffered spike bitmasks
__device__ float          g_vsum[H];
__device__ unsigned       g_barA = 0u;
__device__ unsigned       g_barG = 0u;

// ---------------- grid barrier: fence + arrive in tid 0 -----------------------
__device__ __forceinline__ void grid_sync() {
    __syncthreads();
    if (threadIdx.x == 0) {
        __threadfence();                                  // release block's writes
        unsigned gen = *((volatile unsigned*)&g_barG);
        unsigned a = atomicAdd(&g_barA, 1u);
        if (a == NBLK - 1u) {
            g_barA = 0u;
            __threadfence();
            atomicAdd(&g_barG, 1u);
        } else {
            while (*((volatile unsigned*)&g_barG) == gen) { }
        }
        __threadfence();                                  // acquire
    }
    __syncthreads();
}

// ---------------- single fused persistent kernel ------------------------------
__global__ void __launch_bounds__(TPB, 1) reservoir_kernel(
    const float* __restrict__ x,      // [100,512]
    const float* __restrict__ win,    // [512,4096]
    const float* __restrict__ W,      // [4096,4096]
    const float* __restrict__ Rw,     // [4096,64]
    const float* __restrict__ Rb,     // [64]
    const int*   __restrict__ delays, // [4096,4096]
    float* __restrict__ out)          // [64]
{
    __shared__ float          s_acc[9 * 32 * 32];  // 36 KB [d][lane][w^lane]
    __shared__ unsigned short s_dense[H];          // 8 KB dense spike list
    __shared__ float          s_ring[ND][32];      // block-local delay ring
    __shared__ int            s_ns;

    const int tid  = threadIdx.x;
    const int b    = blockIdx.x;
    const int lane = tid & 31;
    const int wrp  = tid >> 5;
    const int col0 = b << 5;
    const float*         Wb = W + col0 + lane;     // per-lane column base
    const unsigned char* Db = g_DPK + col0 + lane;

    // ---------------- prologue: input GEMM (blocks 0-39) / delay pack --------
    if (b < 40) {
        float* xs = s_acc;
        int t0 = (b >> 2) * 10;
        int j  = ((b & 3) << 10) + tid;
        for (int idx = tid; idx < 10 * IN_DIM; idx += TPB)
            xs[idx] = x[t0 * IN_DIM + idx];
        __syncthreads();
        float a[10];
#pragma unroll
        for (int tt = 0; tt < 10; tt++) a[tt] = 0.f;
        for (int k = 0; k < IN_DIM; k++) {
            float wv = __ldg(&win[k * H + j]);
#pragma unroll
            for (int tt = 0; tt < 10; tt++) a[tt] += xs[tt * IN_DIM + k] * wv;
        }
#pragma unroll
        for (int tt = 0; tt < 10; tt++) g_IIN[(t0 + tt) * H + j] = a[tt];
        __syncthreads();
    } else {
        const int4* dl = (const int4*)delays;
        uchar4* dp = (uchar4*)g_DPK;
        for (int idx = (b - 40) * TPB + tid; idx < H * H / 4; idx += 88 * TPB) {
            int4 d4 = dl[idx];
            dp[idx] = make_uchar4((unsigned char)d4.x, (unsigned char)d4.y,
                                  (unsigned char)d4.z, (unsigned char)d4.w);
        }
    }
    if (tid < ND * 32) ((float*)s_ring)[tid] = 0.f;

    float v = 0.f, gam = 1.f, rate = 0.f, vsum = 0.f;

    // phase A (warp 0 only): LIF update for block's 32 neurons, publish ballot
    auto phaseA = [&](int t, float iin) {
        float irec = s_ring[t % ND][lane];
        s_ring[t % ND][lane] = 0.f;
        float itot = __fmul_rn(__fadd_rn(iin, irec), gam);
        v = __fadd_rn(__fmul_rn(v, DECAY_F), itot);
        bool sp = (v >= 1.0f);
        if (sp) v = 0.f;
        float spf = sp ? 1.f : 0.f;
        rate = __fadd_rn(__fmul_rn(0.9f, rate), __fmul_rn(0.1f, spf));
        gam  = __fadd_rn(gam, __fmul_rn(0.01f, __fadd_rn(0.1f, -rate)));
        gam  = fminf(fmaxf(gam, 0.5f), 2.0f);
        vsum += v;
        unsigned m = __ballot_sync(0xffffffffu, sp);
        if (lane == 0) __stcg(&g_mask[t & 1][b], m);
    };

    grid_sync();                    // prologue data visible everywhere
    if (wrp == 0) phaseA(0, __ldcg(&g_IIN[col0 + lane]));
    grid_sync();                    // step-0 masks published

    for (int t = 0; t < NSTEPS - 1; t++) {
        const int par  = t & 1;
        const int slot = t % ND;

        float iin_next = 0.f;
        if (wrp == 0) iin_next = __ldcg(&g_IIN[(t + 1) * H + col0 + lane]);

        if (wrp == 0) {
            // ---- warp 0: dense spike list from 128 ballot words ----
            uint4 mw = __ldcg(&((const uint4*)g_mask[par])[lane]);
            int c0 = __popc(mw.x), c1 = __popc(mw.y);
            int c2 = __popc(mw.z), c3 = __popc(mw.w);
            int ssum = c0 + c1 + c2 + c3;
            int inc = ssum;
#pragma unroll
            for (int o = 1; o < 32; o <<= 1) {
                int nv = __shfl_up_sync(0xffffffffu, inc, o);
                if (lane >= o) inc += nv;
            }
            int off = inc - ssum;
            int nb  = lane << 7;              // neuron base of this lane's 4 words
            unsigned mm;
            mm = mw.x; while (mm) { int bi = __ffs(mm) - 1; mm &= mm - 1;
                s_dense[off++] = (unsigned short)(nb + bi); }
            mm = mw.y; while (mm) { int bi = __ffs(mm) - 1; mm &= mm - 1;
                s_dense[off++] = (unsigned short)(nb + 32 + bi); }
            mm = mw.z; while (mm) { int bi = __ffs(mm) - 1; mm &= mm - 1;
                s_dense[off++] = (unsigned short)(nb + 64 + bi); }
            mm = mw.w; while (mm) { int bi = __ffs(mm) - 1; mm &= mm - 1;
                s_dense[off++] = (unsigned short)(nb + 96 + bi); }
            if (lane == 31) s_ns = inc;
        } else {
            // ---- warps 1-31: zero all accumulators in parallel ----
            for (int i = tid - 32; i < 9 * 32 * 32; i += TPB - 32) s_acc[i] = 0.f;
        }
        __syncthreads();

        // ---- scatter: warp = spike, lane = column; 4x unrolled (MLP 8) ----
        const int ns  = s_ns;
        const int swz = (lane << 5) + (wrp ^ lane);   // conflict-free slice
        int k = wrp;
        for (; k + 96 < ns; k += 128) {
            int i0 = s_dense[k],      i1 = s_dense[k + 32];
            int i2 = s_dense[k + 64], i3 = s_dense[k + 96];
            float w0 = __ldcg(Wb + (i0 << 12));
            float w1 = __ldcg(Wb + (i1 << 12));
            float w2 = __ldcg(Wb + (i2 << 12));
            float w3 = __ldcg(Wb + (i3 << 12));
            int d0 = (int)__ldg(Db + (i0 << 12));
            int d1 = (int)__ldg(Db + (i1 << 12));
            int d2 = (int)__ldg(Db + (i2 << 12));
            int d3 = (int)__ldg(Db + (i3 << 12));
            s_acc[((d0 - 1) << 10) + swz] += w0;
            s_acc[((d1 - 1) << 10) + swz] += w1;
            s_acc[((d2 - 1) << 10) + swz] += w2;
            s_acc[((d3 - 1) << 10) + swz] += w3;
        }
        for (; k < ns; k += 32) {
            int i0 = s_dense[k];
            float w0 = __ldcg(Wb + (i0 << 12));
            int d0 = (int)__ldg(Db + (i0 << 12));
            s_acc[((d0 - 1) << 10) + swz] += w0;
        }
        __syncthreads();

        // ---- reduce warp-partials into ring; warp 0 then runs phase A ------
        if (tid < 288) {                      // warps 0-8: delay d = wrp
            int d = tid >> 5, l2 = tid & 31;
            const float* base = &s_acc[(d << 10) + (l2 << 5)];
            float s = 0.f;
#pragma unroll
            for (int ww = 0; ww < 32; ww++) s += base[ww ^ l2];
            int s2 = slot + d + 1;
            if (s2 >= ND) s2 -= ND;
            s_ring[s2][l2] += s;
        }
        // warp 0 wrote ring slot (t+1)%ND itself (d=0) -> in-order, no sync
        if (wrp == 0) phaseA(t + 1, iin_next);
        grid_sync();                          // masks t+1 published; s_acc reads done
    }

    // ---------------- epilogue: readout ----------------
    if (wrp == 0) __stcg(&g_vsum[col0 + lane], vsum);
    grid_sync();

    if (b == 0) {
        float* s_red = s_acc;
        int o = tid & 63, q = tid >> 6;               // 16 partials per output
        float s = 0.f;
        for (int jj = q * 256; jj < q * 256 + 256; jj++) {
            float vm = __ldcg(&g_vsum[jj]) / 100.0f;
            s += vm * __ldg(&Rw[jj * OUT_DIM + o]);
        }
        s_red[tid] = s;
        __syncthreads();
        if (tid < OUT_DIM) {
            float tot = 0.f;
#pragma unroll
            for (int q2 = 0; q2 < 16; q2++) tot += s_red[q2 * 64 + tid];
            out[tid] = tot + __ldg(&Rb[tid]);
        }
    }
}

// ---------------- host launch: ONE kernel -------------------------------------
extern "C" void kernel_launch(void* const* d_in, const int* in_sizes, int n_in,
                              void* d_out, int out_size) {
    const float* x      = (const float*)d_in[0];
    const float* win    = (const float*)d_in[1];
    const float* W      = (const float*)d_in[2];
    const float* Rw     = (const float*)d_in[3];
    const float* Rb     = (const float*)d_in[4];
    const int*   delays = (const int*)d_in[5];
    (void)in_sizes; (void)n_in; (void)out_size;

    reservoir_kernel<<<NBLK, TPB>>>(x, win, W, Rw, Rb, delays, (float*)d_out);
}

// round 16
// speedup vs baseline: 2.6281x; 1.0192x over previous
#include <cuda_runtime.h>
#include <cuda_bf16.h>
#include <cstdint>

#define H        4096
#define NSTEPS   100
#define IN_DIM   512
#define OUT_DIM  64
#define ND       10
#define NBLK     128          // persistent blocks; block owns 32 cols + 32 neurons
#define TPB      1024
#define DECAY_F  0.9512294245007141f

// ---------------- static device state ----------------------------------------
__device__ float          g_IIN[NSTEPS * H];       // input currents (1.6 MB)
__device__ unsigned char  g_DPK[(size_t)H * H];    // byte delays 1..9 (16 MB)
__device__ unsigned       g_mask[2][NBLK];         // parity-buffered spike ballots
__device__ float          g_vsum[H];
__device__ int            g_arr[NBLK];             // flag-barrier arrivals
__device__ int            g_rel;                   // flag-barrier release word
__device__ unsigned       g_barA = 0u;             // atomic barrier (2 uses)
__device__ unsigned       g_barG = 0u;

// ---------------- atomic grid barrier (prologue/epilogue only) ----------------
__device__ __forceinline__ void grid_sync() {
    __syncthreads();
    if (threadIdx.x == 0) {
        __threadfence();
        unsigned gen = *((volatile unsigned*)&g_barG);
        unsigned a = atomicAdd(&g_barA, 1u);
        if (a == NBLK - 1u) {
            g_barA = 0u;
            __threadfence();
            atomicAdd(&g_barG, 1u);
        } else {
            while (*((volatile unsigned*)&g_barG) == gen) { }
        }
        __threadfence();
    }
    __syncthreads();
}

// ---------------- flag barrier: parallel arrive, block-0 aggregate ------------
// epoch must be strictly increasing within a launch (1..NSTEPS-1)
__device__ __forceinline__ void step_sync(int b, int lane, int epoch) {
    __syncthreads();
    if (threadIdx.x == 0) {
        __threadfence();                              // release block's writes
        *((volatile int*)&g_arr[b]) = epoch;          // parallel arrival
    }
    if (b == 0 && threadIdx.x < 32) {                 // block 0 warp 0 aggregates
        const volatile int* va = (const volatile int*)g_arr;
        for (;;) {
            int m0 = va[lane], m1 = va[lane + 32];
            int m2 = va[lane + 64], m3 = va[lane + 96];
            int mn = min(min(m0, m1), min(m2, m3));
            if (__ballot_sync(0xffffffffu, mn >= epoch) == 0xffffffffu) break;
        }
        __threadfence();
        if (lane == 0) *((volatile int*)&g_rel) = epoch;
    }
    if (threadIdx.x == 0) {
        while (*((volatile int*)&g_rel) < epoch) { }
        __threadfence();                              // acquire
    }
    __syncthreads();
}

// ---------------- single fused persistent kernel ------------------------------
__global__ void __launch_bounds__(TPB, 1) reservoir_kernel(
    const float* __restrict__ x,      // [100,512]
    const float* __restrict__ win,    // [512,4096]
    const float* __restrict__ W,      // [4096,4096]
    const float* __restrict__ Rw,     // [4096,64]
    const float* __restrict__ Rb,     // [64]
    const int*   __restrict__ delays, // [4096,4096]
    float* __restrict__ out)          // [64]
{
    __shared__ float          s_acc[9 * 32 * 32];  // 36 KB [d][lane][warp^lane]
    __shared__ unsigned short s_dense[H];          // 8 KB dense spike list
    __shared__ float          s_ring[ND][32];      // block-local delay ring
    __shared__ int            s_ns;

    const int tid  = threadIdx.x;
    const int b    = blockIdx.x;
    const int lane = tid & 31;
    const int wrp  = tid >> 5;
    const int col0 = b << 5;
    const float*         Wb = W + col0 + lane;     // per-lane column base
    const unsigned char* Db = g_DPK + col0 + lane;

    // ---------------- prologue: input GEMM (blocks 0-39) / delay pack --------
    if (b < 40) {
        float* xs = s_acc;
        int t0 = (b >> 2) * 10;
        int j  = ((b & 3) << 10) + tid;
        for (int idx = tid; idx < 10 * IN_DIM; idx += TPB)
            xs[idx] = x[t0 * IN_DIM + idx];
        __syncthreads();
        float a[10];
#pragma unroll
        for (int tt = 0; tt < 10; tt++) a[tt] = 0.f;
        for (int k = 0; k < IN_DIM; k++) {
            float wv = __ldg(&win[k * H + j]);
#pragma unroll
            for (int tt = 0; tt < 10; tt++) a[tt] += xs[tt * IN_DIM + k] * wv;
        }
#pragma unroll
        for (int tt = 0; tt < 10; tt++) g_IIN[(t0 + tt) * H + j] = a[tt];
        __syncthreads();
    } else {
        const int4* dl = (const int4*)delays;
        uchar4* dp = (uchar4*)g_DPK;
        for (int idx = (b - 40) * TPB + tid; idx < H * H / 4; idx += 88 * TPB) {
            int4 d4 = dl[idx];
            dp[idx] = make_uchar4((unsigned char)d4.x, (unsigned char)d4.y,
                                  (unsigned char)d4.z, (unsigned char)d4.w);
        }
    }
    if (tid < ND * 32) ((float*)s_ring)[tid] = 0.f;
    if (tid == 0) {                                   // replay-safe barrier reset
        *((volatile int*)&g_arr[b]) = 0;
        if (b == 0) *((volatile int*)&g_rel) = 0;
    }

    float v = 0.f, gam = 1.f, rate = 0.f, vsum = 0.f;

    // phase A (warp 0 only): LIF update for block's 32 neurons, publish ballot
    auto phaseA = [&](int t, float iin) {
        float irec = s_ring[t % ND][lane];
        s_ring[t % ND][lane] = 0.f;
        float itot = __fmul_rn(__fadd_rn(iin, irec), gam);
        v = __fadd_rn(__fmul_rn(v, DECAY_F), itot);
        bool sp = (v >= 1.0f);
        if (sp) v = 0.f;
        float spf = sp ? 1.f : 0.f;
        rate = __fadd_rn(__fmul_rn(0.9f, rate), __fmul_rn(0.1f, spf));
        gam  = __fadd_rn(gam, __fmul_rn(0.01f, __fadd_rn(0.1f, -rate)));
        gam  = fminf(fmaxf(gam, 0.5f), 2.0f);
        vsum += v;
        unsigned m = __ballot_sync(0xffffffffu, sp);
        if (lane == 0) __stcg(&g_mask[t & 1][b], m);
    };

    grid_sync();                    // prologue data + barrier resets visible
    if (wrp == 0) phaseA(0, __ldcg(&g_IIN[col0 + lane]));
    grid_sync();                    // step-0 masks published

    for (int t = 0; t < NSTEPS - 1; t++) {
        const int par  = t & 1;
        const int slot = t % ND;

        float iin_next = 0.f;
        if (wrp == 0) iin_next = __ldcg(&g_IIN[(t + 1) * H + col0 + lane]);

        if (wrp == 0) {
            // ---- warp 0: dense spike list from 128 ballot words ----
            uint4 mw = __ldcg(&((const uint4*)g_mask[par])[lane]);
            int c0 = __popc(mw.x), c1 = __popc(mw.y);
            int c2 = __popc(mw.z), c3 = __popc(mw.w);
            int ssum = c0 + c1 + c2 + c3;
            int inc = ssum;
#pragma unroll
            for (int o = 1; o < 32; o <<= 1) {
                int nv = __shfl_up_sync(0xffffffffu, inc, o);
                if (lane >= o) inc += nv;
            }
            int off = inc - ssum;
            int nb  = lane << 7;
            unsigned mm;
            mm = mw.x; while (mm) { int bi = __ffs(mm) - 1; mm &= mm - 1;
                s_dense[off++] = (unsigned short)(nb + bi); }
            mm = mw.y; while (mm) { int bi = __ffs(mm) - 1; mm &= mm - 1;
                s_dense[off++] = (unsigned short)(nb + 32 + bi); }
            mm = mw.z; while (mm) { int bi = __ffs(mm) - 1; mm &= mm - 1;
                s_dense[off++] = (unsigned short)(nb + 64 + bi); }
            mm = mw.w; while (mm) { int bi = __ffs(mm) - 1; mm &= mm - 1;
                s_dense[off++] = (unsigned short)(nb + 96 + bi); }
            if (lane == 31) s_ns = inc;
        } else {
            // ---- warps 1-31: zero all accumulators in parallel ----
            for (int i = tid - 32; i < 9 * 32 * 32; i += TPB - 32) s_acc[i] = 0.f;
        }
        __syncthreads();

        // ---- scatter: warp = spike, lane = column; 4x unrolled (MLP 8) ----
        const int ns  = s_ns;
        const int swz = (lane << 5) + (wrp ^ lane);   // conflict-free slice
        int k = wrp;
        for (; k + 96 < ns; k += 128) {
            int i0 = s_dense[k],      i1 = s_dense[k + 32];
            int i2 = s_dense[k + 64], i3 = s_dense[k + 96];
            float w0 = __ldcg(Wb + (i0 << 12));
            float w1 = __ldcg(Wb + (i1 << 12));
            float w2 = __ldcg(Wb + (i2 << 12));
            float w3 = __ldcg(Wb + (i3 << 12));
            int d0 = (int)__ldg(Db + (i0 << 12));
            int d1 = (int)__ldg(Db + (i1 << 12));
            int d2 = (int)__ldg(Db + (i2 << 12));
            int d3 = (int)__ldg(Db + (i3 << 12));
            s_acc[((d0 - 1) << 10) + swz] += w0;
            s_acc[((d1 - 1) << 10) + swz] += w1;
            s_acc[((d2 - 1) << 10) + swz] += w2;
            s_acc[((d3 - 1) << 10) + swz] += w3;
        }
        for (; k < ns; k += 32) {
            int i0 = s_dense[k];
            float w0 = __ldcg(Wb + (i0 << 12));
            int d0 = (int)__ldg(Db + (i0 << 12));
            s_acc[((d0 - 1) << 10) + swz] += w0;
        }
        __syncthreads();

        // ---- reduce warp-partials into ring; warp 0 then runs phase A ------
        if (tid < 288) {                      // warps 0-8: delay = (tid>>5)+1
            int d = tid >> 5, l2 = tid & 31;
            const float* base = &s_acc[(d << 10) + (l2 << 5)];
            float s = 0.f;
#pragma unroll
            for (int ww = 0; ww < 32; ww++) s += base[ww ^ l2];
            int s2 = slot + d + 1;
            if (s2 >= ND) s2 -= ND;
            s_ring[s2][l2] += s;
        }
        // warp 0 wrote ring slot (t+1)%ND itself (d=0) -> in-order, no sync
        if (wrp == 0) phaseA(t + 1, iin_next);
        step_sync(b, lane, t + 1);            // masks t+1 published; s_acc safe
    }

    // ---------------- epilogue: readout ----------------
    if (wrp == 0) __stcg(&g_vsum[col0 + lane], vsum);
    grid_sync();

    if (b == 0) {
        float* s_red = s_acc;
        int o = tid & 63, q = tid >> 6;       // 16 partials per output
        float s = 0.f;
        for (int jj = q * 256; jj < q * 256 + 256; jj++) {
            float vm = __ldcg(&g_vsum[jj]) / 100.0f;
            s += vm * __ldg(&Rw[jj * OUT_DIM + o]);
        }
        s_red[tid] = s;
        __syncthreads();
        if (tid < OUT_DIM) {
            float tot = 0.f;
#pragma unroll
            for (int q2 = 0; q2 < 16; q2++) tot += s_red[q2 * 64 + tid];
            out[tid] = tot + __ldg(&Rb[tid]);
        }
    }
}

// ---------------- host launch: ONE kernel -------------------------------------
extern "C" void kernel_launch(void* const* d_in, const int* in_sizes, int n_in,
                              void* d_out, int out_size) {
    const float* x      = (const float*)d_in[0];
    const float* win    = (const float*)d_in[1];
    const float* W      = (const float*)d_in[2];
    const float* Rw     = (const float*)d_in[3];
    const float* Rb     = (const float*)d_in[4];
    const int*   delays = (const int*)d_in[5];
    (void)in_sizes; (void)n_in; (void)out_size;

    reservoir_kernel<<<NBLK, TPB>>>(x, win, W, Rw, Rb, delays, (float*)d_out);
}